// round 15
// baseline (speedup 1.0000x reference)
#include <cuda_runtime.h>
#include <cuda_fp16.h>
#include <cstdint>

#define ZDIM 8
#define HDIM 64
#define NEG 0.01f
#define LEN 510
#define NTOT 32640            /* 64 * 510 = 255 * 128 */
#define LOG_OFF (NTOT*ZDIM)
#define CTA 128

#define SCL1 32.0f            /* W1 tile scale (lo terms -> fp16 normal range) */
#define SCL2 32.0f            /* W2 tile scale */
#define SCLC 1024.0f          /* W2c tile scale */
#define INV1 (1.0f/32.0f)
#define INV2 (1.0f/32.0f)
#define INVC (1.0f/1024.0f)

#define S1 80                 /* phase-1 tile row stride, bytes */
#define S2 144                /* phase-2 tile row stride, bytes */

/* ---- smem byte offsets ---- */
#define R_EH   0              /* E hi [128] rows 64B @ stride 80 = 10240 */
#define R_EL   10240
#define R_B1H  20480          /* W1^T hi [64][32]h = 5120 */
#define R_B1L  25600
#define R_A2H  0              /* h hi [128][72]h = 18432 (aliases E after L1) */
#define R_A2L  18432
#define R_MSK  36864          /* mask {1,0} fp16 */
#define R_W2H  55296          /* W2^T hi [64][72]h = 9216 */
#define R_W2L  64512
#define R_WCH  73728          /* W2c^T = (cw*W2)^T hi */
#define R_WCL  82944
#define MISC   92160
#define M_B1   (MISC+0)
#define M_B2   (MISC+256)
#define M_W3   (MISC+512)
#define M_W3N  (MISC+768)
#define M_CW   (MISC+1024)
#define M_XT   (MISC+1280)    /* float[128] */
#define M_B3   (MISC+1792)
#define M_TCOL (MISC+2048)    /* float[64]: Tcol_j = sum_i cw_i*W2[i][j] (unscaled fp32) */
#define SMEM_BYTES (MISC+2560)

__device__ float g_dlog[ZDIM * NTOT];

__device__ __forceinline__ uint32_t smem_u32(const void* p){
    uint32_t a;
    asm("{ .reg .u64 t; cvta.to.shared.u64 t, %1; cvt.u32.u64 %0, t; }" : "=r"(a) : "l"(p));
    return a;
}
__device__ __forceinline__ void ldsm4(uint32_t& r0, uint32_t& r1, uint32_t& r2, uint32_t& r3, uint32_t addr){
    asm volatile("ldmatrix.sync.aligned.m8n8.x4.shared.b16 {%0,%1,%2,%3}, [%4];"
                 : "=r"(r0), "=r"(r1), "=r"(r2), "=r"(r3) : "r"(addr));
}
__device__ __forceinline__ void mma16(float* c, const uint32_t* a, uint32_t b0, uint32_t b1){
    asm volatile("mma.sync.aligned.m16n8k16.row.col.f32.f16.f16.f32 "
                 "{%0,%1,%2,%3}, {%4,%5,%6,%7}, {%8,%9}, {%0,%1,%2,%3};"
                 : "+f"(c[0]), "+f"(c[1]), "+f"(c[2]), "+f"(c[3])
                 : "r"(a[0]), "r"(a[1]), "r"(a[2]), "r"(a[3]), "r"(b0), "r"(b1));
}
__device__ __forceinline__ float leaky(float p){
    return fmaxf(p, 0.f) + NEG * fminf(p, 0.f);
}
__device__ __forceinline__ void pack8(const float* v, uint4& hi, uint4& lo){
    __half2* hp = reinterpret_cast<__half2*>(&hi);
    __half2* lp = reinterpret_cast<__half2*>(&lo);
    #pragma unroll
    for (int p = 0; p < 4; p++){
        float a = v[2*p], b = v[2*p+1];
        __half ah = __float2half_rn(a), bh = __float2half_rn(b);
        __half al = __float2half_rn(a - __half2float(ah));
        __half bl = __float2half_rn(b - __half2float(bh));
        hp[p] = __halves2half2(ah, bh);
        lp[p] = __halves2half2(al, bl);
    }
}
__device__ __forceinline__ uint32_t h2u(__half a, __half b){
    __half2 v = __halves2half2(a, b);
    return *reinterpret_cast<uint32_t*>(&v);
}

__global__ __launch_bounds__(CTA, 2)
void mlp_jvp_fp16(const float* __restrict__ x,
                  const float* __restrict__ emb,
                  const float* __restrict__ W1,
                  const float* __restrict__ b1,
                  const float* __restrict__ W2,
                  const float* __restrict__ b2,
                  const float* __restrict__ W3,
                  const float* __restrict__ b3,
                  float* __restrict__ out)
{
    extern __shared__ char smc[];
    const uint32_t sb = smem_u32(smc);
    const int tid = threadIdx.x;
    const int z   = blockIdx.y;

    /* ---- stage: E rows + xt; B1 = 32*W1^T; 32*W2^T, 1024*W2c^T, Tcol ---- */
    {
        const int n   = blockIdx.x * CTA + tid;
        const int bb  = n / LEN;
        const int tt  = n - bb * LEN;
        const int src = bb * 512 + tt + 2;           /* LL=512, LAGS=2 */
        const float4* e4 = reinterpret_cast<const float4*>(emb + (size_t)src * 32);
        float v[32];
        #pragma unroll
        for (int q = 0; q < 8; q++){
            float4 f = __ldg(e4 + q);
            v[4*q] = f.x; v[4*q+1] = f.y; v[4*q+2] = f.z; v[4*q+3] = f.w;
        }
        #pragma unroll
        for (int grp = 0; grp < 4; grp++){
            uint4 hi, lo; pack8(v + 8*grp, hi, lo);
            *reinterpret_cast<uint4*>(smc + R_EH + tid*S1 + grp*16) = hi;
            *reinterpret_cast<uint4*>(smc + R_EL + tid*S1 + grp*16) = lo;
        }
        reinterpret_cast<float*>(smc + M_XT)[tid] = x[src * ZDIM + z];
    }
    if (tid < 64){
        const float* g2 = W2 + z*HDIM*HDIM;
        const float* g1 = W1 + z*33*HDIM;
        const float* cwg = g1 + 32*HDIM;
        float v[64], vc[64];
        float tsum = 0.f;
        #pragma unroll 8
        for (int i = 0; i < 64; i++){
            float w = g2[i*64 + tid];
            float c = __ldg(cwg + i) * w;
            v[i]  = SCL2 * w;                        /* scaled: lo stays fp16-normal */
            vc[i] = SCLC * c;
            tsum += c;                               /* Tcol_j exact fp32 (unscaled) */
        }
        #pragma unroll
        for (int grp = 0; grp < 8; grp++){
            uint4 hi, lo; pack8(v + 8*grp, hi, lo);
            *reinterpret_cast<uint4*>(smc + R_W2H + tid*S2 + grp*16) = hi;
            *reinterpret_cast<uint4*>(smc + R_W2L + tid*S2 + grp*16) = lo;
            pack8(vc + 8*grp, hi, lo);
            *reinterpret_cast<uint4*>(smc + R_WCH + tid*S2 + grp*16) = hi;
            *reinterpret_cast<uint4*>(smc + R_WCL + tid*S2 + grp*16) = lo;
        }
        reinterpret_cast<float*>(smc + M_TCOL)[tid] = tsum;
        reinterpret_cast<float*>(smc + M_B1)[tid] = b1[z*HDIM + tid];
        reinterpret_cast<float*>(smc + M_B2)[tid] = b2[z*HDIM + tid];
        float w3v = W3[z*HDIM + tid];
        reinterpret_cast<float*>(smc + M_W3)[tid]  = w3v;
        reinterpret_cast<float*>(smc + M_W3N)[tid] = NEG * w3v;
        reinterpret_cast<float*>(smc + M_CW)[tid]  = cwg[tid];
        if (tid == 0) *reinterpret_cast<float*>(smc + M_B3) = b3[z];
    } else {
        const int h = tid - 64;
        const float* g1 = W1 + z*33*HDIM;
        float v[32];
        #pragma unroll 8
        for (int e = 0; e < 32; e++) v[e] = SCL1 * g1[e*64 + h];
        #pragma unroll
        for (int grp = 0; grp < 4; grp++){
            uint4 hi, lo; pack8(v + 8*grp, hi, lo);
            *reinterpret_cast<uint4*>(smc + R_B1H + h*S1 + grp*16) = hi;
            *reinterpret_cast<uint4*>(smc + R_B1L + h*S1 + grp*16) = lo;
        }
    }
    __syncthreads();

    const int wid  = tid >> 5;
    const int lane = tid & 31;
    const int g    = lane >> 2;
    const int c    = lane & 3;
    const int rowbase = wid * 32;
    const int lm   = lane >> 3;
    const int rr   = lane & 7;
    const int rowadd = (lm & 1) * 8;
    const int coladd = (lm >> 1) * 16;

    /* ---- layer 1: 32*pre1 = [128x32] @ (32*W1^T), 3xFP16 split ---- */
    float C1[2][8][4];
    {
        const float* b1f = reinterpret_cast<const float*>(smc + M_B1);
        #pragma unroll
        for (int nf = 0; nf < 8; nf++){
            float bj0 = SCL1 * b1f[nf*8 + 2*c], bj1 = SCL1 * b1f[nf*8 + 2*c + 1];
            #pragma unroll
            for (int mf = 0; mf < 2; mf++){
                C1[mf][nf][0] = bj0; C1[mf][nf][1] = bj1;
                C1[mf][nf][2] = bj0; C1[mf][nf][3] = bj1;
            }
        }
        uint32_t aEh = sb + R_EH + (uint32_t)(rowbase + rowadd + rr)*S1 + coladd;
        uint32_t aEl = aEh + (R_EL - R_EH);
        uint32_t aB1 = sb + R_B1H + (uint32_t)rr*S1 + (lm & 1)*16 + (lm >> 1)*(R_B1L - R_B1H);
        #pragma unroll
        for (int kb = 0; kb < 2; kb++){
            uint32_t Ah[2][4], Al[2][4];
            #pragma unroll
            for (int mf = 0; mf < 2; mf++){
                ldsm4(Ah[mf][0], Ah[mf][1], Ah[mf][2], Ah[mf][3], aEh + mf*16*S1 + kb*32);
                ldsm4(Al[mf][0], Al[mf][1], Al[mf][2], Al[mf][3], aEl + mf*16*S1 + kb*32);
            }
            #pragma unroll
            for (int nf = 0; nf < 8; nf++){
                uint32_t bh0, bh1, bl0, bl1;
                ldsm4(bh0, bh1, bl0, bl1, aB1 + nf*8*S1 + kb*32);
                #pragma unroll
                for (int mf = 0; mf < 2; mf++){
                    mma16(C1[mf][nf], Ah[mf], bh0, bh1);
                    mma16(C1[mf][nf], Al[mf], bh0, bh1);
                    mma16(C1[mf][nf], Ah[mf], bl0, bl1);
                }
            }
        }
    }
    __syncthreads();

    /* ---- epilogue 1: pre1 = C1/32 + xt*cw (exact); h hi/lo + {1,0} mask ---- */
    {
        const float* cwf = reinterpret_cast<const float*>(smc + M_CW);
        const float* xtf = reinterpret_cast<const float*>(smc + M_XT);
        const __half one  = __float2half_rn(1.0f);
        const __half zero = __float2half_rn(0.0f);
        #pragma unroll
        for (int mf = 0; mf < 2; mf++){
            #pragma unroll
            for (int hr = 0; hr < 2; hr++){
                const int r  = rowbase + mf*16 + g + hr*8;
                const float xr = xtf[r];
                #pragma unroll
                for (int nf = 0; nf < 8; nf++){
                    const int j0 = nf*8 + 2*c;
                    float p0 = fmaf(xr, cwf[j0],   INV1 * C1[mf][nf][2*hr + 0]);
                    float p1 = fmaf(xr, cwf[j0+1], INV1 * C1[mf][nf][2*hr + 1]);
                    float h0 = leaky(p0), h1 = leaky(p1);
                    __half hh0 = __float2half_rn(h0);
                    __half hh1 = __float2half_rn(h1);
                    __half hl0 = __float2half_rn(h0 - __half2float(hh0));
                    __half hl1 = __float2half_rn(h1 - __half2float(hh1));
                    bool s0 = (p0 >= 0.f), s1 = (p1 >= 0.f);
                    char* base = smc + r*S2 + j0*2;
                    *reinterpret_cast<uint32_t*>(base + R_A2H) = h2u(hh0, hh1);
                    *reinterpret_cast<uint32_t*>(base + R_A2L) = h2u(hl0, hl1);
                    *reinterpret_cast<uint32_t*>(base + R_MSK) = h2u(s0 ? one : zero, s1 ? one : zero);
                }
            }
        }
    }
    __syncthreads();

    /* ---- layer 2: fwd (3-term, W2*32) + tangent (mask @ W2c*1024, 2-term) ---- */
    float Cf[2][8][4], Ct[2][8][4];
    {
        const float* b2f = reinterpret_cast<const float*>(smc + M_B2);
        #pragma unroll
        for (int nf = 0; nf < 8; nf++){
            float bj0 = SCL2 * b2f[nf*8 + 2*c], bj1 = SCL2 * b2f[nf*8 + 2*c + 1];
            #pragma unroll
            for (int mf = 0; mf < 2; mf++){
                Cf[mf][nf][0] = bj0; Cf[mf][nf][1] = bj1;
                Cf[mf][nf][2] = bj0; Cf[mf][nf][3] = bj1;
                Ct[mf][nf][0] = 0.f; Ct[mf][nf][1] = 0.f;
                Ct[mf][nf][2] = 0.f; Ct[mf][nf][3] = 0.f;
            }
        }
        uint32_t aAh = sb + R_A2H + (uint32_t)(rowbase + rowadd + rr)*S2 + coladd;
        uint32_t aAl = aAh + (R_A2L - R_A2H);
        uint32_t aTm = aAh + (R_MSK - R_A2H);
        uint32_t aW  = sb + R_W2H + (uint32_t)rr*S2 + (lm & 1)*16 + (lm >> 1)*(R_W2L - R_W2H);
        uint32_t aC  = sb + R_WCH + (uint32_t)rr*S2 + (lm & 1)*16 + (lm >> 1)*(R_WCL - R_WCH);
        #pragma unroll
        for (int kb = 0; kb < 4; kb++){
            uint32_t Ah[2][4], Al[2][4], Tm[2][4];
            #pragma unroll
            for (int mf = 0; mf < 2; mf++){
                ldsm4(Ah[mf][0], Ah[mf][1], Ah[mf][2], Ah[mf][3], aAh + mf*16*S2 + kb*32);
                ldsm4(Al[mf][0], Al[mf][1], Al[mf][2], Al[mf][3], aAl + mf*16*S2 + kb*32);
                ldsm4(Tm[mf][0], Tm[mf][1], Tm[mf][2], Tm[mf][3], aTm + mf*16*S2 + kb*32);
            }
            #pragma unroll
            for (int nf = 0; nf < 8; nf++){
                uint32_t bh0, bh1, bl0, bl1, ch0, ch1, cl0, cl1;
                ldsm4(bh0, bh1, bl0, bl1, aW + nf*8*S2 + kb*32);
                ldsm4(ch0, ch1, cl0, cl1, aC + nf*8*S2 + kb*32);
                #pragma unroll
                for (int mf = 0; mf < 2; mf++){
                    mma16(Cf[mf][nf], Ah[mf], bh0, bh1);
                    mma16(Cf[mf][nf], Al[mf], bh0, bh1);
                    mma16(Cf[mf][nf], Ah[mf], bl0, bl1);
                    mma16(Ct[mf][nf], Tm[mf], ch0, ch1);
                    mma16(Ct[mf][nf], Tm[mf], cl0, cl1);
                }
            }
        }
    }

    /* ---- fused epilogue: pre2 = Cf/32; dpre2 = 0.99*Ct/1024 + 0.01*Tcol ---- */
    const float* w3f  = reinterpret_cast<const float*>(smc + M_W3);
    const float* w3n  = reinterpret_cast<const float*>(smc + M_W3N);
    const float* tcol = reinterpret_cast<const float*>(smc + M_TCOL);
    float opart[4] = {0.f, 0.f, 0.f, 0.f};
    float dpart[4] = {0.f, 0.f, 0.f, 0.f};
    #pragma unroll
    for (int mf = 0; mf < 2; mf++)
    #pragma unroll
    for (int nf = 0; nf < 8; nf++)
    #pragma unroll
    for (int e = 0; e < 4; e++){
        float v = INV2 * Cf[mf][nf][e];
        int rs = mf*2 + (e>>1);
        int j  = nf*8 + 2*c + (e&1);
        float t = fmaf(Ct[mf][nf][e], 0.99f * INVC, 0.01f * tcol[j]);
        bool s = (v >= 0.f);
        float h2 = s ? v : NEG * v;
        opart[rs] = fmaf(h2, w3f[j], opart[rs]);
        dpart[rs] = fmaf(s ? w3f[j] : w3n[j], t, dpart[rs]);
    }

    /* quad reduction and writeback */
    const float b3v = *reinterpret_cast<const float*>(smc + M_B3);
    #pragma unroll
    for (int rs = 0; rs < 4; rs++){
        float v = opart[rs];
        v += __shfl_xor_sync(0xffffffffu, v, 1);
        v += __shfl_xor_sync(0xffffffffu, v, 2);
        float d = dpart[rs];
        d += __shfl_xor_sync(0xffffffffu, d, 1);
        d += __shfl_xor_sync(0xffffffffu, d, 2);
        if (c == 0){
            int row  = rowbase + (rs>>1)*16 + (rs&1)*8 + g;
            int nrow = blockIdx.x * CTA + row;
            out[(size_t)nrow * ZDIM + z] = v + b3v;
            g_dlog[z*NTOT + nrow] = __logf(fabsf(d));
        }
    }
}

__global__ void logdet_reduce4(float* __restrict__ out){
    int t = blockIdx.x * blockDim.x + threadIdx.x;
    if (t >= NTOT/4) return;
    int base = t * 4;
    float4 s = make_float4(0.f, 0.f, 0.f, 0.f);
    #pragma unroll
    for (int zz = 0; zz < ZDIM; zz++){
        float4 v = *reinterpret_cast<const float4*>(&g_dlog[zz*NTOT + base]);
        s.x += v.x; s.y += v.y; s.z += v.z; s.w += v.w;
    }
    *reinterpret_cast<float4*>(&out[LOG_OFF + base]) = s;
}

extern "C" void kernel_launch(void* const* d_in, const int* in_sizes, int n_in,
                              void* d_out, int out_size){
    const float* x    = (const float*)d_in[0];
    const float* embv = (const float*)d_in[1];
    const float* W1   = (const float*)d_in[2];
    const float* b1   = (const float*)d_in[3];
    const float* W2   = (const float*)d_in[4];
    const float* b2   = (const float*)d_in[5];
    const float* W3   = (const float*)d_in[6];
    const float* b3   = (const float*)d_in[7];
    float* out = (float*)d_out;

    cudaFuncSetAttribute(mlp_jvp_fp16, cudaFuncAttributeMaxDynamicSharedMemorySize, SMEM_BYTES);
    dim3 grid(NTOT / CTA, ZDIM);
    mlp_jvp_fp16<<<grid, CTA, SMEM_BYTES>>>(x, embv, W1, b1, W2, b2, W3, b3, out);
    logdet_reduce4<<<(NTOT/4 + 255)/256, 256>>>(out);
}

// round 16
// speedup vs baseline: 1.1242x; 1.1242x over previous
#include <cuda_runtime.h>
#include <cuda_fp16.h>
#include <cstdint>

#define ZDIM 8
#define HDIM 64
#define NEG 0.01f
#define LEN 510
#define NTOT 32640            /* 64 * 510 = 255 * 128 */
#define LOG_OFF (NTOT*ZDIM)
#define CTA 128

#define SCL1 32.0f
#define SCL2 32.0f
#define SCLC 1024.0f
#define INV1 (1.0f/32.0f)
#define INV2 (1.0f/32.0f)
#define INVC (1.0f/1024.0f)

#define S1 80                 /* phase-1 tile row stride, bytes */
#define S2 144                /* phase-2 tile row stride, bytes */

/* ---- smem byte offsets ---- */
#define R_EH   0              /* E hi [128] rows @ stride 80 = 10240 */
#define R_EL   10240
#define R_B1H  20480          /* W1^T hi */
#define R_B1L  25600
#define R_A2H  0              /* h hi (aliases E after L1) */
#define R_A2L  18432
#define R_MSK  36864
#define R_W2H  55296
#define R_W2L  64512
#define R_WCH  73728
#define R_WCL  82944
#define MISC   92160
#define M_B1   (MISC+0)
#define M_B2   (MISC+256)
#define M_W3   (MISC+512)
#define M_W3N  (MISC+768)
#define M_CW   (MISC+1024)
#define M_TCOL (MISC+1280)
#define M_B3   (MISC+1536)
#define M_XT   (MISC+2048)    /* float[128], NOT in prep image */
#define SMEM_BYTES (MISC+2560)

/* ---- prep image layout: [B1 10240][W2-group 36864][MISC 2048] = 49152 B ---- */
#define IW_B1  0
#define IW_W2  10240
#define IW_MI  47104
#define WIMG_BYTES 49152
#define EIMG_BYTES 20480      /* [E hi 10240][E lo 10240] */

__device__ __align__(16) unsigned char g_wimg[ZDIM][WIMG_BYTES];
__device__ __align__(16) unsigned char g_eimg[255][EIMG_BYTES];
__device__ float g_dlog[ZDIM * NTOT];

__device__ __forceinline__ uint32_t smem_u32(const void* p){
    uint32_t a;
    asm("{ .reg .u64 t; cvta.to.shared.u64 t, %1; cvt.u32.u64 %0, t; }" : "=r"(a) : "l"(p));
    return a;
}
__device__ __forceinline__ void ldsm4(uint32_t& r0, uint32_t& r1, uint32_t& r2, uint32_t& r3, uint32_t addr){
    asm volatile("ldmatrix.sync.aligned.m8n8.x4.shared.b16 {%0,%1,%2,%3}, [%4];"
                 : "=r"(r0), "=r"(r1), "=r"(r2), "=r"(r3) : "r"(addr));
}
__device__ __forceinline__ void mma16(float* c, const uint32_t* a, uint32_t b0, uint32_t b1){
    asm volatile("mma.sync.aligned.m16n8k16.row.col.f32.f16.f16.f32 "
                 "{%0,%1,%2,%3}, {%4,%5,%6,%7}, {%8,%9}, {%0,%1,%2,%3};"
                 : "+f"(c[0]), "+f"(c[1]), "+f"(c[2]), "+f"(c[3])
                 : "r"(a[0]), "r"(a[1]), "r"(a[2]), "r"(a[3]), "r"(b0), "r"(b1));
}
__device__ __forceinline__ float leaky(float p){
    return fmaxf(p, 0.f) + NEG * fminf(p, 0.f);
}
__device__ __forceinline__ void pack8(const float* v, uint4& hi, uint4& lo){
    __half2* hp = reinterpret_cast<__half2*>(&hi);
    __half2* lp = reinterpret_cast<__half2*>(&lo);
    #pragma unroll
    for (int p = 0; p < 4; p++){
        float a = v[2*p], b = v[2*p+1];
        __half ah = __float2half_rn(a), bh = __float2half_rn(b);
        __half al = __float2half_rn(a - __half2float(ah));
        __half bl = __float2half_rn(b - __half2float(bh));
        hp[p] = __halves2half2(ah, bh);
        lp[p] = __halves2half2(al, bl);
    }
}
__device__ __forceinline__ uint32_t h2u(__half a, __half b){
    __half2 v = __halves2half2(a, b);
    return *reinterpret_cast<uint32_t*>(&v);
}

/* ================= prep: build tile byte-images ONCE per replay ============ */
__global__ void prep_kernel(const float* __restrict__ emb,
                            const float* __restrict__ W1,
                            const float* __restrict__ b1,
                            const float* __restrict__ W2,
                            const float* __restrict__ b2,
                            const float* __restrict__ W3,
                            const float* __restrict__ b3)
{
    const int bx  = blockIdx.x;
    const int tid = threadIdx.x;

    if (bx < ZDIM){
        const int z = bx;
        unsigned char* img = g_wimg[z];
        if (tid < 64){
            const float* g2 = W2 + z*HDIM*HDIM;
            const float* g1 = W1 + z*33*HDIM;
            const float* cwg = g1 + 32*HDIM;
            float v[64], vc[64];
            float tsum = 0.f;
            #pragma unroll 8
            for (int i = 0; i < 64; i++){
                float w = g2[i*64 + tid];
                float c = __ldg(cwg + i) * w;
                v[i]  = SCL2 * w;
                vc[i] = SCLC * c;
                tsum += c;
            }
            #pragma unroll
            for (int grp = 0; grp < 8; grp++){
                uint4 hi, lo; pack8(v + 8*grp, hi, lo);
                *reinterpret_cast<uint4*>(img + IW_W2 + 0     + tid*S2 + grp*16) = hi;  /* W2H */
                *reinterpret_cast<uint4*>(img + IW_W2 + 9216  + tid*S2 + grp*16) = lo;  /* W2L */
                pack8(vc + 8*grp, hi, lo);
                *reinterpret_cast<uint4*>(img + IW_W2 + 18432 + tid*S2 + grp*16) = hi;  /* WCH */
                *reinterpret_cast<uint4*>(img + IW_W2 + 27648 + tid*S2 + grp*16) = lo;  /* WCL */
            }
            unsigned char* mi = img + IW_MI;
            reinterpret_cast<float*>(mi + 0)[tid]    = b1[z*HDIM + tid];
            reinterpret_cast<float*>(mi + 256)[tid]  = b2[z*HDIM + tid];
            float w3v = W3[z*HDIM + tid];
            reinterpret_cast<float*>(mi + 512)[tid]  = w3v;
            reinterpret_cast<float*>(mi + 768)[tid]  = NEG * w3v;
            reinterpret_cast<float*>(mi + 1024)[tid] = cwg[tid];
            reinterpret_cast<float*>(mi + 1280)[tid] = tsum;
            if (tid == 0) *reinterpret_cast<float*>(mi + 1536) = b3[z];
        } else {
            const int h = tid - 64;
            const float* g1 = W1 + z*33*HDIM;
            float v[32];
            #pragma unroll 8
            for (int e = 0; e < 32; e++) v[e] = SCL1 * g1[e*64 + h];
            #pragma unroll
            for (int grp = 0; grp < 4; grp++){
                uint4 hi, lo; pack8(v + 8*grp, hi, lo);
                *reinterpret_cast<uint4*>(img + IW_B1 + h*S1 + grp*16)        = hi;
                *reinterpret_cast<uint4*>(img + IW_B1 + 5120 + h*S1 + grp*16) = lo;
            }
        }
    } else {
        const int eb  = bx - ZDIM;                   /* 0..254 */
        unsigned char* img = g_eimg[eb];
        const int n   = eb * CTA + tid;
        const int bb  = n / LEN;
        const int tt  = n - bb * LEN;
        const int src = bb * 512 + tt + 2;           /* LL=512, LAGS=2 */
        const float4* e4 = reinterpret_cast<const float4*>(emb + (size_t)src * 32);
        float v[32];
        #pragma unroll
        for (int q = 0; q < 8; q++){
            float4 f = __ldg(e4 + q);
            v[4*q] = f.x; v[4*q+1] = f.y; v[4*q+2] = f.z; v[4*q+3] = f.w;
        }
        #pragma unroll
        for (int grp = 0; grp < 4; grp++){
            uint4 hi, lo; pack8(v + 8*grp, hi, lo);
            *reinterpret_cast<uint4*>(img + tid*S1 + grp*16)         = hi;
            *reinterpret_cast<uint4*>(img + 10240 + tid*S1 + grp*16) = lo;
        }
    }
}

/* ========================= main kernel ==================================== */
__global__ __launch_bounds__(CTA, 2)
void mlp_jvp_fp16(const float* __restrict__ x,
                  float* __restrict__ out)
{
    extern __shared__ char smc[];
    const uint32_t sb = smem_u32(smc);
    const int tid = threadIdx.x;
    const int z   = blockIdx.y;
    const int bx  = blockIdx.x;

    /* ---- staging = pure copies of precomputed images ---- */
    {
        uint4* s4 = reinterpret_cast<uint4*>(smc);
        const uint4* ei = reinterpret_cast<const uint4*>(g_eimg[bx]);
        const uint4* wi = reinterpret_cast<const uint4*>(g_wimg[z]);
        #pragma unroll
        for (int i = 0; i < 10; i++)  s4[tid + i*CTA]        = ei[tid + i*CTA];        /* E hi+lo: 1280 */
        #pragma unroll
        for (int i = 0; i < 5; i++)   s4[1280 + tid + i*CTA] = wi[tid + i*CTA];        /* B1: 640 */
        #pragma unroll
        for (int i = 0; i < 18; i++)  s4[3456 + tid + i*CTA] = wi[640 + tid + i*CTA];  /* W2 group: 2304 */
        s4[5760 + tid] = wi[2944 + tid];                                               /* MISC: 128 */
        const int n   = bx * CTA + tid;
        const int bb  = n / LEN;
        const int tt  = n - bb * LEN;
        const int src = bb * 512 + tt + 2;
        reinterpret_cast<float*>(smc + M_XT)[tid] = x[src * ZDIM + z];
    }
    __syncthreads();

    const int wid  = tid >> 5;
    const int lane = tid & 31;
    const int g    = lane >> 2;
    const int c    = lane & 3;
    const int rowbase = wid * 32;
    const int lm   = lane >> 3;
    const int rr   = lane & 7;
    const int rowadd = (lm & 1) * 8;
    const int coladd = (lm >> 1) * 16;

    /* ---- layer 1: 32*pre1 = [128x32] @ (32*W1^T), 3xFP16 split ---- */
    float C1[2][8][4];
    {
        const float* b1f = reinterpret_cast<const float*>(smc + M_B1);
        #pragma unroll
        for (int nf = 0; nf < 8; nf++){
            float bj0 = SCL1 * b1f[nf*8 + 2*c], bj1 = SCL1 * b1f[nf*8 + 2*c + 1];
            #pragma unroll
            for (int mf = 0; mf < 2; mf++){
                C1[mf][nf][0] = bj0; C1[mf][nf][1] = bj1;
                C1[mf][nf][2] = bj0; C1[mf][nf][3] = bj1;
            }
        }
        uint32_t aEh = sb + R_EH + (uint32_t)(rowbase + rowadd + rr)*S1 + coladd;
        uint32_t aEl = aEh + (R_EL - R_EH);
        uint32_t aB1 = sb + R_B1H + (uint32_t)rr*S1 + (lm & 1)*16 + (lm >> 1)*(R_B1L - R_B1H);
        #pragma unroll
        for (int kb = 0; kb < 2; kb++){
            uint32_t Ah[2][4], Al[2][4];
            #pragma unroll
            for (int mf = 0; mf < 2; mf++){
                ldsm4(Ah[mf][0], Ah[mf][1], Ah[mf][2], Ah[mf][3], aEh + mf*16*S1 + kb*32);
                ldsm4(Al[mf][0], Al[mf][1], Al[mf][2], Al[mf][3], aEl + mf*16*S1 + kb*32);
            }
            #pragma unroll
            for (int nf = 0; nf < 8; nf++){
                uint32_t bh0, bh1, bl0, bl1;
                ldsm4(bh0, bh1, bl0, bl1, aB1 + nf*8*S1 + kb*32);
                #pragma unroll
                for (int mf = 0; mf < 2; mf++){
                    mma16(C1[mf][nf], Ah[mf], bh0, bh1);
                    mma16(C1[mf][nf], Al[mf], bh0, bh1);
                    mma16(C1[mf][nf], Ah[mf], bl0, bl1);
                }
            }
        }
    }
    __syncthreads();

    /* ---- epilogue 1: pre1 = C1/32 + xt*cw (exact); h hi/lo + {1,0} mask ---- */
    {
        const float* cwf = reinterpret_cast<const float*>(smc + M_CW);
        const float* xtf = reinterpret_cast<const float*>(smc + M_XT);
        const __half one  = __float2half_rn(1.0f);
        const __half zero = __float2half_rn(0.0f);
        #pragma unroll
        for (int mf = 0; mf < 2; mf++){
            #pragma unroll
            for (int hr = 0; hr < 2; hr++){
                const int r  = rowbase + mf*16 + g + hr*8;
                const float xr = xtf[r];
                #pragma unroll
                for (int nf = 0; nf < 8; nf++){
                    const int j0 = nf*8 + 2*c;
                    float p0 = fmaf(xr, cwf[j0],   INV1 * C1[mf][nf][2*hr + 0]);
                    float p1 = fmaf(xr, cwf[j0+1], INV1 * C1[mf][nf][2*hr + 1]);
                    float h0 = leaky(p0), h1 = leaky(p1);
                    __half hh0 = __float2half_rn(h0);
                    __half hh1 = __float2half_rn(h1);
                    __half hl0 = __float2half_rn(h0 - __half2float(hh0));
                    __half hl1 = __float2half_rn(h1 - __half2float(hh1));
                    bool s0 = (p0 >= 0.f), s1 = (p1 >= 0.f);
                    char* base = smc + r*S2 + j0*2;
                    *reinterpret_cast<uint32_t*>(base + R_A2H) = h2u(hh0, hh1);
                    *reinterpret_cast<uint32_t*>(base + R_A2L) = h2u(hl0, hl1);
                    *reinterpret_cast<uint32_t*>(base + R_MSK) = h2u(s0 ? one : zero, s1 ? one : zero);
                }
            }
        }
    }
    __syncthreads();

    /* ---- layer 2: fwd (3-term, W2*32) + tangent (mask @ W2c*1024, 2-term) ---- */
    float Cf[2][8][4], Ct[2][8][4];
    {
        const float* b2f = reinterpret_cast<const float*>(smc + M_B2);
        #pragma unroll
        for (int nf = 0; nf < 8; nf++){
            float bj0 = SCL2 * b2f[nf*8 + 2*c], bj1 = SCL2 * b2f[nf*8 + 2*c + 1];
            #pragma unroll
            for (int mf = 0; mf < 2; mf++){
                Cf[mf][nf][0] = bj0; Cf[mf][nf][1] = bj1;
                Cf[mf][nf][2] = bj0; Cf[mf][nf][3] = bj1;
                Ct[mf][nf][0] = 0.f; Ct[mf][nf][1] = 0.f;
                Ct[mf][nf][2] = 0.f; Ct[mf][nf][3] = 0.f;
            }
        }
        uint32_t aAh = sb + R_A2H + (uint32_t)(rowbase + rowadd + rr)*S2 + coladd;
        uint32_t aAl = aAh + (R_A2L - R_A2H);
        uint32_t aTm = aAh + (R_MSK - R_A2H);
        uint32_t aW  = sb + R_W2H + (uint32_t)rr*S2 + (lm & 1)*16 + (lm >> 1)*(R_W2L - R_W2H);
        uint32_t aC  = sb + R_WCH + (uint32_t)rr*S2 + (lm & 1)*16 + (lm >> 1)*(R_WCL - R_WCH);
        #pragma unroll
        for (int kb = 0; kb < 4; kb++){
            uint32_t Ah[2][4], Al[2][4], Tm[2][4];
            #pragma unroll
            for (int mf = 0; mf < 2; mf++){
                ldsm4(Ah[mf][0], Ah[mf][1], Ah[mf][2], Ah[mf][3], aAh + mf*16*S2 + kb*32);
                ldsm4(Al[mf][0], Al[mf][1], Al[mf][2], Al[mf][3], aAl + mf*16*S2 + kb*32);
                ldsm4(Tm[mf][0], Tm[mf][1], Tm[mf][2], Tm[mf][3], aTm + mf*16*S2 + kb*32);
            }
            #pragma unroll
            for (int nf = 0; nf < 8; nf++){
                uint32_t bh0, bh1, bl0, bl1, ch0, ch1, cl0, cl1;
                ldsm4(bh0, bh1, bl0, bl1, aW + nf*8*S2 + kb*32);
                ldsm4(ch0, ch1, cl0, cl1, aC + nf*8*S2 + kb*32);
                #pragma unroll
                for (int mf = 0; mf < 2; mf++){
                    mma16(Cf[mf][nf], Ah[mf], bh0, bh1);
                    mma16(Cf[mf][nf], Al[mf], bh0, bh1);
                    mma16(Cf[mf][nf], Ah[mf], bl0, bl1);
                    mma16(Ct[mf][nf], Tm[mf], ch0, ch1);
                    mma16(Ct[mf][nf], Tm[mf], cl0, cl1);
                }
            }
        }
    }

    /* ---- fused epilogue: pre2 = Cf/32; dpre2 = 0.99*Ct/1024 + 0.01*Tcol ---- */
    const float* w3f  = reinterpret_cast<const float*>(smc + M_W3);
    const float* w3n  = reinterpret_cast<const float*>(smc + M_W3N);
    const float* tcol = reinterpret_cast<const float*>(smc + M_TCOL);
    float opart[4] = {0.f, 0.f, 0.f, 0.f};
    float dpart[4] = {0.f, 0.f, 0.f, 0.f};
    #pragma unroll
    for (int mf = 0; mf < 2; mf++)
    #pragma unroll
    for (int nf = 0; nf < 8; nf++)
    #pragma unroll
    for (int e = 0; e < 4; e++){
        float v = INV2 * Cf[mf][nf][e];
        int rs = mf*2 + (e>>1);
        int j  = nf*8 + 2*c + (e&1);
        float t = fmaf(Ct[mf][nf][e], 0.99f * INVC, 0.01f * tcol[j]);
        bool s = (v >= 0.f);
        float h2 = s ? v : NEG * v;
        opart[rs] = fmaf(h2, w3f[j], opart[rs]);
        dpart[rs] = fmaf(s ? w3f[j] : w3n[j], t, dpart[rs]);
    }

    /* quad reduction and writeback */
    const float b3v = *reinterpret_cast<const float*>(smc + M_B3);
    #pragma unroll
    for (int rs = 0; rs < 4; rs++){
        float v = opart[rs];
        v += __shfl_xor_sync(0xffffffffu, v, 1);
        v += __shfl_xor_sync(0xffffffffu, v, 2);
        float d = dpart[rs];
        d += __shfl_xor_sync(0xffffffffu, d, 1);
        d += __shfl_xor_sync(0xffffffffu, d, 2);
        if (c == 0){
            int row  = rowbase + (rs>>1)*16 + (rs&1)*8 + g;
            int nrow = bx * CTA + row;
            out[(size_t)nrow * ZDIM + z] = v + b3v;
            g_dlog[z*NTOT + nrow] = __logf(fabsf(d));
        }
    }
}

__global__ void logdet_reduce4(float* __restrict__ out){
    int t = blockIdx.x * blockDim.x + threadIdx.x;
    if (t >= NTOT/4) return;
    int base = t * 4;
    float4 s = make_float4(0.f, 0.f, 0.f, 0.f);
    #pragma unroll
    for (int zz = 0; zz < ZDIM; zz++){
        float4 v = *reinterpret_cast<const float4*>(&g_dlog[zz*NTOT + base]);
        s.x += v.x; s.y += v.y; s.z += v.z; s.w += v.w;
    }
    *reinterpret_cast<float4*>(&out[LOG_OFF + base]) = s;
}

extern "C" void kernel_launch(void* const* d_in, const int* in_sizes, int n_in,
                              void* d_out, int out_size){
    const float* x    = (const float*)d_in[0];
    const float* embv = (const float*)d_in[1];
    const float* W1   = (const float*)d_in[2];
    const float* b1   = (const float*)d_in[3];
    const float* W2   = (const float*)d_in[4];
    const float* b2   = (const float*)d_in[5];
    const float* W3   = (const float*)d_in[6];
    const float* b3   = (const float*)d_in[7];
    float* out = (float*)d_out;

    prep_kernel<<<ZDIM + 255, CTA>>>(embv, W1, b1, W2, b2, W3, b3);

    cudaFuncSetAttribute(mlp_jvp_fp16, cudaFuncAttributeMaxDynamicSharedMemorySize, SMEM_BYTES);
    dim3 grid(255, ZDIM);
    mlp_jvp_fp16<<<grid, CTA, SMEM_BYTES>>>(x, out);
    logdet_reduce4<<<(NTOT/4 + 255)/256, 256>>>(out);
}

// round 17
// speedup vs baseline: 1.1627x; 1.0343x over previous
#include <cuda_runtime.h>
#include <cuda_fp16.h>
#include <cstdint>

#define ZDIM 8
#define HDIM 64
#define NEG 0.01f
#define LEN 510
#define NTOT 32640            /* 64 * 510 = 255 * 128 */
#define LOG_OFF (NTOT*ZDIM)
#define CTA 128

#define SCL1 32.0f
#define SCL2 32.0f
#define SCLC 1024.0f
#define INV1 (1.0f/32.0f)
#define INV2 (1.0f/32.0f)
#define INVC (1.0f/1024.0f)

#define S1 80                 /* phase-1 tile row stride, bytes */
#define S2 144                /* phase-2 tile row stride, bytes */

/* ---- smem byte offsets (main kernel) ---- */
#define R_EH   0
#define R_EL   10240
#define R_B1H  20480
#define R_B1L  25600
#define R_A2H  0
#define R_A2L  18432
#define R_MSK  36864
#define R_W2H  55296
#define R_W2L  64512
#define R_WCH  73728
#define R_WCL  82944
#define MISC   92160
#define M_B1   (MISC+0)
#define M_B2   (MISC+256)
#define M_W3   (MISC+512)
#define M_W3N  (MISC+768)
#define M_CW   (MISC+1024)
#define M_TCOL (MISC+1280)
#define M_B3   (MISC+1536)
#define M_XT   (MISC+2048)
#define SMEM_BYTES (MISC+2560)

/* ---- prep image layout: [B1 10240][W2-group 36864][MISC 2048] = 49152 B ---- */
#define IW_B1  0
#define IW_W2  10240
#define IW_MI  47104
#define WIMG_BYTES 49152
#define EIMG_BYTES 20480      /* [E hi 10240][E lo 10240] */

__device__ __align__(16) unsigned char g_wimg[ZDIM][WIMG_BYTES];
__device__ __align__(16) unsigned char g_eimg[255][EIMG_BYTES];
__device__ float g_dlog[ZDIM * NTOT];

__device__ __forceinline__ uint32_t smem_u32(const void* p){
    uint32_t a;
    asm("{ .reg .u64 t; cvta.to.shared.u64 t, %1; cvt.u32.u64 %0, t; }" : "=r"(a) : "l"(p));
    return a;
}
__device__ __forceinline__ void ldsm4(uint32_t& r0, uint32_t& r1, uint32_t& r2, uint32_t& r3, uint32_t addr){
    asm volatile("ldmatrix.sync.aligned.m8n8.x4.shared.b16 {%0,%1,%2,%3}, [%4];"
                 : "=r"(r0), "=r"(r1), "=r"(r2), "=r"(r3) : "r"(addr));
}
__device__ __forceinline__ void mma16(float* c, const uint32_t* a, uint32_t b0, uint32_t b1){
    asm volatile("mma.sync.aligned.m16n8k16.row.col.f32.f16.f16.f32 "
                 "{%0,%1,%2,%3}, {%4,%5,%6,%7}, {%8,%9}, {%0,%1,%2,%3};"
                 : "+f"(c[0]), "+f"(c[1]), "+f"(c[2]), "+f"(c[3])
                 : "r"(a[0]), "r"(a[1]), "r"(a[2]), "r"(a[3]), "r"(b0), "r"(b1));
}
__device__ __forceinline__ float leaky(float p){
    return fmaxf(p, 0.f) + NEG * fminf(p, 0.f);
}
__device__ __forceinline__ void pack8(const float* v, uint4& hi, uint4& lo){
    __half2* hp = reinterpret_cast<__half2*>(&hi);
    __half2* lp = reinterpret_cast<__half2*>(&lo);
    #pragma unroll
    for (int p = 0; p < 4; p++){
        float a = v[2*p], b = v[2*p+1];
        __half ah = __float2half_rn(a), bh = __float2half_rn(b);
        __half al = __float2half_rn(a - __half2float(ah));
        __half bl = __float2half_rn(b - __half2float(bh));
        hp[p] = __halves2half2(ah, bh);
        lp[p] = __halves2half2(al, bl);
    }
}
__device__ __forceinline__ uint32_t h2u(__half a, __half b){
    __half2 v = __halves2half2(a, b);
    return *reinterpret_cast<uint32_t*>(&v);
}

/* ============ prep: build tile byte-images, parallelized (256 thr) ========= */
__global__ void prep_kernel(const float* __restrict__ emb,
                            const float* __restrict__ W1,
                            const float* __restrict__ b1,
                            const float* __restrict__ W2,
                            const float* __restrict__ b2,
                            const float* __restrict__ W3,
                            const float* __restrict__ b3)
{
    const int bx  = blockIdx.x;
    const int tid = threadIdx.x;

    if (bx < ZDIM){
        __shared__ float st[128];                    /* Tcol partials */
        const int z = bx;
        unsigned char* img = g_wimg[z];
        const float* g2 = W2 + z*HDIM*HDIM;
        const float* g1 = W1 + z*33*HDIM;
        const float* cwg = g1 + 32*HDIM;

        if (tid < 128){
            /* W2 / W2c pack: 2 threads per column j, i-halves */
            const int j    = tid & 63;
            const int half = tid >> 6;               /* i in [half*32, half*32+32) */
            float v[32], vc[32];
            float tsum = 0.f;
            #pragma unroll 8
            for (int q = 0; q < 32; q++){
                int i = half*32 + q;
                float w = g2[i*64 + j];
                float cc = __ldg(cwg + i) * w;
                v[q]  = SCL2 * w;
                vc[q] = SCLC * cc;
                tsum += cc;
            }
            st[tid] = tsum;
            #pragma unroll
            for (int grp = 0; grp < 4; grp++){
                uint4 hi, lo; pack8(v + 8*grp, hi, lo);
                int go = (half*4 + grp) * 16;
                *reinterpret_cast<uint4*>(img + IW_W2 + 0     + j*S2 + go) = hi;  /* W2H */
                *reinterpret_cast<uint4*>(img + IW_W2 + 9216  + j*S2 + go) = lo;  /* W2L */
                pack8(vc + 8*grp, hi, lo);
                *reinterpret_cast<uint4*>(img + IW_W2 + 18432 + j*S2 + go) = hi;  /* WCH */
                *reinterpret_cast<uint4*>(img + IW_W2 + 27648 + j*S2 + go) = lo;  /* WCL */
            }
        } else if (tid < 192){
            /* B1[h][e] = 32*W1[e][h] */
            const int h = tid - 128;
            float v[32];
            #pragma unroll 8
            for (int e = 0; e < 32; e++) v[e] = SCL1 * g1[e*64 + h];
            #pragma unroll
            for (int grp = 0; grp < 4; grp++){
                uint4 hi, lo; pack8(v + 8*grp, hi, lo);
                *reinterpret_cast<uint4*>(img + IW_B1 + h*S1 + grp*16)        = hi;
                *reinterpret_cast<uint4*>(img + IW_B1 + 5120 + h*S1 + grp*16) = lo;
            }
        } else {
            /* misc scalars */
            const int hh = tid - 192;
            unsigned char* mi = img + IW_MI;
            reinterpret_cast<float*>(mi + 0)[hh]    = b1[z*HDIM + hh];
            reinterpret_cast<float*>(mi + 256)[hh]  = b2[z*HDIM + hh];
            float w3v = W3[z*HDIM + hh];
            reinterpret_cast<float*>(mi + 512)[hh]  = w3v;
            reinterpret_cast<float*>(mi + 768)[hh]  = NEG * w3v;
            reinterpret_cast<float*>(mi + 1024)[hh] = cwg[hh];
            if (hh == 0) *reinterpret_cast<float*>(mi + 1536) = b3[z];
        }
        __syncthreads();
        if (tid >= 192){                             /* Tcol = partial0 + partial1 */
            const int hh = tid - 192;
            reinterpret_cast<float*>(img + IW_MI + 1280)[hh] = st[hh] + st[hh + 64];
        }
    } else {
        /* E image: 2 threads per row (half rows) */
        const int eb   = bx - ZDIM;                  /* 0..254 */
        unsigned char* img = g_eimg[eb];
        const int row  = tid >> 1;
        const int half = tid & 1;
        const int n    = eb * CTA + row;
        const int bb   = n / LEN;
        const int tt   = n - bb * LEN;
        const int src  = bb * 512 + tt + 2;          /* LL=512, LAGS=2 */
        const float4* e4 = reinterpret_cast<const float4*>(emb + (size_t)src * 32) + half*4;
        float v[16];
        #pragma unroll
        for (int q = 0; q < 4; q++){
            float4 f = __ldg(e4 + q);
            v[4*q] = f.x; v[4*q+1] = f.y; v[4*q+2] = f.z; v[4*q+3] = f.w;
        }
        #pragma unroll
        for (int grp = 0; grp < 2; grp++){
            uint4 hi, lo; pack8(v + 8*grp, hi, lo);
            int go = (half*2 + grp) * 16;
            *reinterpret_cast<uint4*>(img + row*S1 + go)         = hi;
            *reinterpret_cast<uint4*>(img + 10240 + row*S1 + go) = lo;
        }
    }
}

/* ========================= main kernel ==================================== */
__global__ __launch_bounds__(CTA, 2)
void mlp_jvp_fp16(const float* __restrict__ x,
                  float* __restrict__ out)
{
    extern __shared__ char smc[];
    const uint32_t sb = smem_u32(smc);
    const int tid = threadIdx.x;
    const int z   = blockIdx.y;
    const int bx  = blockIdx.x;

    /* ---- staging = pure copies of precomputed images ---- */
    {
        uint4* s4 = reinterpret_cast<uint4*>(smc);
        const uint4* ei = reinterpret_cast<const uint4*>(g_eimg[bx]);
        const uint4* wi = reinterpret_cast<const uint4*>(g_wimg[z]);
        #pragma unroll
        for (int i = 0; i < 10; i++)  s4[tid + i*CTA]        = ei[tid + i*CTA];
        #pragma unroll
        for (int i = 0; i < 5; i++)   s4[1280 + tid + i*CTA] = wi[tid + i*CTA];
        #pragma unroll
        for (int i = 0; i < 18; i++)  s4[3456 + tid + i*CTA] = wi[640 + tid + i*CTA];
        s4[5760 + tid] = wi[2944 + tid];
        const int n   = bx * CTA + tid;
        const int bb  = n / LEN;
        const int tt  = n - bb * LEN;
        const int src = bb * 512 + tt + 2;
        reinterpret_cast<float*>(smc + M_XT)[tid] = x[src * ZDIM + z];
    }
    __syncthreads();

    const int wid  = tid >> 5;
    const int lane = tid & 31;
    const int g    = lane >> 2;
    const int c    = lane & 3;
    const int rowbase = wid * 32;
    const int lm   = lane >> 3;
    const int rr   = lane & 7;
    const int rowadd = (lm & 1) * 8;
    const int coladd = (lm >> 1) * 16;

    /* ---- layer 1: 32*pre1 = [128x32] @ (32*W1^T), 3xFP16 split ---- */
    float C1[2][8][4];
    {
        const float* b1f = reinterpret_cast<const float*>(smc + M_B1);
        #pragma unroll
        for (int nf = 0; nf < 8; nf++){
            float bj0 = SCL1 * b1f[nf*8 + 2*c], bj1 = SCL1 * b1f[nf*8 + 2*c + 1];
            #pragma unroll
            for (int mf = 0; mf < 2; mf++){
                C1[mf][nf][0] = bj0; C1[mf][nf][1] = bj1;
                C1[mf][nf][2] = bj0; C1[mf][nf][3] = bj1;
            }
        }
        uint32_t aEh = sb + R_EH + (uint32_t)(rowbase + rowadd + rr)*S1 + coladd;
        uint32_t aEl = aEh + (R_EL - R_EH);
        uint32_t aB1 = sb + R_B1H + (uint32_t)rr*S1 + (lm & 1)*16 + (lm >> 1)*(R_B1L - R_B1H);
        #pragma unroll
        for (int kb = 0; kb < 2; kb++){
            uint32_t Ah[2][4], Al[2][4];
            #pragma unroll
            for (int mf = 0; mf < 2; mf++){
                ldsm4(Ah[mf][0], Ah[mf][1], Ah[mf][2], Ah[mf][3], aEh + mf*16*S1 + kb*32);
                ldsm4(Al[mf][0], Al[mf][1], Al[mf][2], Al[mf][3], aEl + mf*16*S1 + kb*32);
            }
            #pragma unroll
            for (int nf = 0; nf < 8; nf++){
                uint32_t bh0, bh1, bl0, bl1;
                ldsm4(bh0, bh1, bl0, bl1, aB1 + nf*8*S1 + kb*32);
                #pragma unroll
                for (int mf = 0; mf < 2; mf++){
                    mma16(C1[mf][nf], Ah[mf], bh0, bh1);
                    mma16(C1[mf][nf], Al[mf], bh0, bh1);
                    mma16(C1[mf][nf], Ah[mf], bl0, bl1);
                }
            }
        }
    }
    __syncthreads();

    /* ---- epilogue 1: pre1 = C1/32 + xt*cw (exact); h hi/lo + {1,0} mask ---- */
    {
        const float* cwf = reinterpret_cast<const float*>(smc + M_CW);
        const float* xtf = reinterpret_cast<const float*>(smc + M_XT);
        const __half one  = __float2half_rn(1.0f);
        const __half zero = __float2half_rn(0.0f);
        #pragma unroll
        for (int mf = 0; mf < 2; mf++){
            #pragma unroll
            for (int hr = 0; hr < 2; hr++){
                const int r  = rowbase + mf*16 + g + hr*8;
                const float xr = xtf[r];
                #pragma unroll
                for (int nf = 0; nf < 8; nf++){
                    const int j0 = nf*8 + 2*c;
                    float p0 = fmaf(xr, cwf[j0],   INV1 * C1[mf][nf][2*hr + 0]);
                    float p1 = fmaf(xr, cwf[j0+1], INV1 * C1[mf][nf][2*hr + 1]);
                    float h0 = leaky(p0), h1 = leaky(p1);
                    __half hh0 = __float2half_rn(h0);
                    __half hh1 = __float2half_rn(h1);
                    __half hl0 = __float2half_rn(h0 - __half2float(hh0));
                    __half hl1 = __float2half_rn(h1 - __half2float(hh1));
                    bool s0 = (p0 >= 0.f), s1 = (p1 >= 0.f);
                    char* base = smc + r*S2 + j0*2;
                    *reinterpret_cast<uint32_t*>(base + R_A2H) = h2u(hh0, hh1);
                    *reinterpret_cast<uint32_t*>(base + R_A2L) = h2u(hl0, hl1);
                    *reinterpret_cast<uint32_t*>(base + R_MSK) = h2u(s0 ? one : zero, s1 ? one : zero);
                }
            }
        }
    }
    __syncthreads();

    /* ---- layer 2: fwd (3-term, W2*32) + tangent (mask @ W2c*1024, 2-term) ---- */
    float Cf[2][8][4], Ct[2][8][4];
    {
        const float* b2f = reinterpret_cast<const float*>(smc + M_B2);
        #pragma unroll
        for (int nf = 0; nf < 8; nf++){
            float bj0 = SCL2 * b2f[nf*8 + 2*c], bj1 = SCL2 * b2f[nf*8 + 2*c + 1];
            #pragma unroll
            for (int mf = 0; mf < 2; mf++){
                Cf[mf][nf][0] = bj0; Cf[mf][nf][1] = bj1;
                Cf[mf][nf][2] = bj0; Cf[mf][nf][3] = bj1;
                Ct[mf][nf][0] = 0.f; Ct[mf][nf][1] = 0.f;
                Ct[mf][nf][2] = 0.f; Ct[mf][nf][3] = 0.f;
            }
        }
        uint32_t aAh = sb + R_A2H + (uint32_t)(rowbase + rowadd + rr)*S2 + coladd;
        uint32_t aAl = aAh + (R_A2L - R_A2H);
        uint32_t aTm = aAh + (R_MSK - R_A2H);
        uint32_t aW  = sb + R_W2H + (uint32_t)rr*S2 + (lm & 1)*16 + (lm >> 1)*(R_W2L - R_W2H);
        uint32_t aC  = sb + R_WCH + (uint32_t)rr*S2 + (lm & 1)*16 + (lm >> 1)*(R_WCL - R_WCH);
        #pragma unroll
        for (int kb = 0; kb < 4; kb++){
            uint32_t Ah[2][4], Al[2][4], Tm[2][4];
            #pragma unroll
            for (int mf = 0; mf < 2; mf++){
                ldsm4(Ah[mf][0], Ah[mf][1], Ah[mf][2], Ah[mf][3], aAh + mf*16*S2 + kb*32);
                ldsm4(Al[mf][0], Al[mf][1], Al[mf][2], Al[mf][3], aAl + mf*16*S2 + kb*32);
                ldsm4(Tm[mf][0], Tm[mf][1], Tm[mf][2], Tm[mf][3], aTm + mf*16*S2 + kb*32);
            }
            #pragma unroll
            for (int nf = 0; nf < 8; nf++){
                uint32_t bh0, bh1, bl0, bl1, ch0, ch1, cl0, cl1;
                ldsm4(bh0, bh1, bl0, bl1, aW + nf*8*S2 + kb*32);
                ldsm4(ch0, ch1, cl0, cl1, aC + nf*8*S2 + kb*32);
                #pragma unroll
                for (int mf = 0; mf < 2; mf++){
                    mma16(Cf[mf][nf], Ah[mf], bh0, bh1);
                    mma16(Cf[mf][nf], Al[mf], bh0, bh1);
                    mma16(Cf[mf][nf], Ah[mf], bl0, bl1);
                    mma16(Ct[mf][nf], Tm[mf], ch0, ch1);
                    mma16(Ct[mf][nf], Tm[mf], cl0, cl1);
                }
            }
        }
    }

    /* ---- fused epilogue: pre2 = Cf/32; dpre2 = 0.99*Ct/1024 + 0.01*Tcol ---- */
    const float* w3f  = reinterpret_cast<const float*>(smc + M_W3);
    const float* w3n  = reinterpret_cast<const float*>(smc + M_W3N);
    const float* tcol = reinterpret_cast<const float*>(smc + M_TCOL);
    float opart[4] = {0.f, 0.f, 0.f, 0.f};
    float dpart[4] = {0.f, 0.f, 0.f, 0.f};
    #pragma unroll
    for (int mf = 0; mf < 2; mf++)
    #pragma unroll
    for (int nf = 0; nf < 8; nf++)
    #pragma unroll
    for (int e = 0; e < 4; e++){
        float v = INV2 * Cf[mf][nf][e];
        int rs = mf*2 + (e>>1);
        int j  = nf*8 + 2*c + (e&1);
        float t = fmaf(Ct[mf][nf][e], 0.99f * INVC, 0.01f * tcol[j]);
        bool s = (v >= 0.f);
        float h2 = s ? v : NEG * v;
        opart[rs] = fmaf(h2, w3f[j], opart[rs]);
        dpart[rs] = fmaf(s ? w3f[j] : w3n[j], t, dpart[rs]);
    }

    /* quad reduction and writeback */
    const float b3v = *reinterpret_cast<const float*>(smc + M_B3);
    #pragma unroll
    for (int rs = 0; rs < 4; rs++){
        float v = opart[rs];
        v += __shfl_xor_sync(0xffffffffu, v, 1);
        v += __shfl_xor_sync(0xffffffffu, v, 2);
        float d = dpart[rs];
        d += __shfl_xor_sync(0xffffffffu, d, 1);
        d += __shfl_xor_sync(0xffffffffu, d, 2);
        if (c == 0){
            int row  = rowbase + (rs>>1)*16 + (rs&1)*8 + g;
            int nrow = bx * CTA + row;
            out[(size_t)nrow * ZDIM + z] = v + b3v;
            g_dlog[z*NTOT + nrow] = __logf(fabsf(d));
        }
    }
}

__global__ void logdet_reduce4(float* __restrict__ out){
    int t = blockIdx.x * blockDim.x + threadIdx.x;
    if (t >= NTOT/4) return;
    int base = t * 4;
    float4 s = make_float4(0.f, 0.f, 0.f, 0.f);
    #pragma unroll
    for (int zz = 0; zz < ZDIM; zz++){
        float4 v = *reinterpret_cast<const float4*>(&g_dlog[zz*NTOT + base]);
        s.x += v.x; s.y += v.y; s.z += v.z; s.w += v.w;
    }
    *reinterpret_cast<float4*>(&out[LOG_OFF + base]) = s;
}

extern "C" void kernel_launch(void* const* d_in, const int* in_sizes, int n_in,
                              void* d_out, int out_size){
    const float* x    = (const float*)d_in[0];
    const float* embv = (const float*)d_in[1];
    const float* W1   = (const float*)d_in[2];
    const float* b1   = (const float*)d_in[3];
    const float* W2   = (const float*)d_in[4];
    const float* b2   = (const float*)d_in[5];
    const float* W3   = (const float*)d_in[6];
    const float* b3   = (const float*)d_in[7];
    float* out = (float*)d_out;

    prep_kernel<<<ZDIM + 255, 256>>>(embv, W1, b1, W2, b2, W3, b3);

    cudaFuncSetAttribute(mlp_jvp_fp16, cudaFuncAttributeMaxDynamicSharedMemorySize, SMEM_BYTES);
    dim3 grid(255, ZDIM);
    mlp_jvp_fp16<<<grid, CTA, SMEM_BYTES>>>(x, out);
    logdet_reduce4<<<(NTOT/4 + 255)/256, 256>>>(out);
}